// round 14
// baseline (speedup 1.0000x reference)
#include <cuda_runtime.h>

// Problem constants (fixed by the dataset)
#define B_   4096
#define H_   256
#define R_   14              // rows per CTA
#define NCTA 293             // ceil(4096/14)
#define HS   16              // h2 row stride in floats (64B, 16B-aligned for LDS.128)

typedef unsigned long long u64;

union F4 { float4 f; u64 u[2]; };
union F2 { float2 f; u64 u; };

// ---------------------------------------------------------------------------
// Device scratch (no dynamic allocation allowed)
// ---------------------------------------------------------------------------
// Whh packed with PRE-DUPLICATED f32x2 gate weights:
//   [k][j][0] = (wi,wi,wf,wf)   [k][j][1] = (wg,wg,wo,wo)
__device__ float4 g_WhhD[256 * 256 * 2];
__device__ float4 g_WihD[3 * 256 * 2];   // same packing
__device__ float4 g_BiasD[256 * 2];      // (bi,bi,bf,bf) | (bg,bg,bo,bo)
__device__ float  g_W2T[256 * 512];      // [k][j]
__device__ float2 g_Wo1D[256 * 128];     // [k][j2] -> (w,w)
__device__ float  g_W1T[7 * 256];        // [k][j]

// ---------------------------------------------------------------------------
// Prep kernel
// ---------------------------------------------------------------------------
__global__ void prep_kernel(const float* __restrict__ W1,
                            const float* __restrict__ W2,
                            const float* __restrict__ Wih,
                            const float* __restrict__ Whh,
                            const float* __restrict__ bih,
                            const float* __restrict__ bhh,
                            const float* __restrict__ Wo1)
{
    int k = blockIdx.x;    // 0..255
    int j = threadIdx.x;   // 0..255

    {
        float wi = Whh[(0   + j) * 256 + k];
        float wf = Whh[(256 + j) * 256 + k];
        float wg = Whh[(512 + j) * 256 + k];
        float wo = Whh[(768 + j) * 256 + k];
        g_WhhD[(k * 256 + j) * 2 + 0] = make_float4(wi, wi, wf, wf);
        g_WhhD[(k * 256 + j) * 2 + 1] = make_float4(wg, wg, wo, wo);
    }
    g_W2T[k * 512 + j]       = W2[(0   + j) * 256 + k];
    g_W2T[k * 512 + 256 + j] = W2[(256 + j) * 256 + k];
    if (j < 128) {
        float w = Wo1[j * 256 + k];
        g_Wo1D[k * 128 + j] = make_float2(w, w);
    }
    if (k < 7)   g_W1T[k * 256 + j] = W1[j * 7 + k];
    if (k < 3) {
        float wi = Wih[(0   + j) * 3 + k];
        float wf = Wih[(256 + j) * 3 + k];
        float wg = Wih[(512 + j) * 3 + k];
        float wo = Wih[(768 + j) * 3 + k];
        g_WihD[(k * 256 + j) * 2 + 0] = make_float4(wi, wi, wf, wf);
        g_WihD[(k * 256 + j) * 2 + 1] = make_float4(wg, wg, wo, wo);
    }
    if (k == 0) {
        float bi = bih[0   + j] + bhh[0   + j];
        float bf = bih[256 + j] + bhh[256 + j];
        float bg = bih[512 + j] + bhh[512 + j];
        float bo = bih[768 + j] + bhh[768 + j];
        g_BiasD[j * 2 + 0] = make_float4(bi, bi, bf, bf);
        g_BiasD[j * 2 + 1] = make_float4(bg, bg, bo, bo);
    }
}

// ---------------------------------------------------------------------------
// Packed f32x2 helpers
// ---------------------------------------------------------------------------
__device__ __forceinline__ u64 fma2(u64 a, u64 b, u64 c) {
    u64 d;
    asm("fma.rn.f32x2 %0, %1, %2, %3;" : "=l"(d) : "l"(a), "l"(b), "l"(c));
    return d;
}
__device__ __forceinline__ u64 dup2(float x) {
    u64 d; unsigned xi = __float_as_uint(x);
    asm("mov.b64 %0, {%1, %2};" : "=l"(d) : "r"(xi), "r"(xi));
    return d;
}
__device__ __forceinline__ u64 pk(float lo, float hi) {
    u64 d;
    asm("mov.b64 %0, {%1, %2};" : "=l"(d)
        : "r"(__float_as_uint(lo)), "r"(__float_as_uint(hi)));
    return d;
}
__device__ __forceinline__ float2 unpk(u64 a) {
    unsigned lo, hi;
    asm("mov.b64 {%0, %1}, %2;" : "=r"(lo), "=r"(hi) : "l"(a));
    return make_float2(__uint_as_float(lo), __uint_as_float(hi));
}

__device__ __forceinline__ float sigmoidf_(float x) {
    return __fdividef(1.f, 1.f + __expf(-x));
}
// branch-free accurate tanh: 1 - 2/(e^{2x}+1); inf-safe, ~1e-6 err
__device__ __forceinline__ float tanhf_(float x) {
    float e = __expf(2.f * x);
    return 1.f - __fdividef(2.f, e + 1.f);
}

// One k-slice: h loads (3 LDS.128 + 1 LDS.64) + 28 FFMA2; weights preloaded,
// pre-duplicated -> ZERO MOVs, LDG result feeds FFMA2 directly.
__device__ __forceinline__ void mac_k(const F4 wA, const F4 wB,
                                      const float* __restrict__ hb,
                                      u64* ai, u64* af, u64* ag, u64* ao)
{
    F4 hA, hB, hC; F2 hD;
    hA.f = *reinterpret_cast<const float4*>(hb);
    hB.f = *reinterpret_cast<const float4*>(hb + 4);
    hC.f = *reinterpret_cast<const float4*>(hb + 8);
    hD.f = *reinterpret_cast<const float2*>(hb + 12);
    u64 h[7] = { hA.u[0], hA.u[1], hB.u[0], hB.u[1], hC.u[0], hC.u[1], hD.u };
    #pragma unroll
    for (int p = 0; p < 7; p++) {
        ai[p] = fma2(h[p], wA.u[0], ai[p]);
        af[p] = fma2(h[p], wA.u[1], af[p]);
        ag[p] = fma2(h[p], wB.u[0], ag[p]);
        ao[p] = fma2(h[p], wB.u[1], ao[p]);
    }
}

// ---------------------------------------------------------------------------
// Main persistent kernel: one CTA handles 14 batch rows end-to-end.
// ---------------------------------------------------------------------------
__global__ void __launch_bounds__(256, 2)
lstm_kernel(const float* __restrict__ meta,
            const float* __restrict__ b1,
            const float* __restrict__ b2,
            const float* __restrict__ bo1,
            const float* __restrict__ Wo2,
            const float* __restrict__ bo2,
            float* __restrict__ out,
            int T_eff)
{
    __shared__ __align__(16) float h2[2][256][HS]; // double-buffered h [buf][k][row]
    __shared__ __align__(16) float xs[3][16];      // [elem][row] current x (fed-back y)
    __shared__ __align__(16) float zb[14][132];    // decoder hidden [row][j2]
    __shared__ float metas[14][8];
    __shared__ __align__(16) float wo2s[3 * 128];
    __shared__ float bo1s[128];
    __shared__ float bo2s[4];

    const int t    = threadIdx.x;
    const int row0 = blockIdx.x * R_;

    // ---- stage small tensors (row indices clamped for the partial last CTA) ----
    if (t < 112) {
        int r = t >> 3, e = t & 7;
        int g = row0 + r; if (g > B_ - 1) g = B_ - 1;
        metas[r][e] = (e < 7) ? meta[g * 7 + e] : 0.f;
    }
    if (t < 128) bo1s[t] = bo1[t];
    wo2s[t] = Wo2[t];
    if (t < 128) wo2s[256 + t] = Wo2[256 + t];
    if (t < 3)   bo2s[t] = bo2[t];
    if (t < 42) {
        int r = t / 3, o = t - 3 * (t / 3);
        int g = row0 + r; if (g > B_ - 1) g = B_ - 1;
        xs[o][r] = meta[g * 7 + o];   // x0 = metadata[:, :3]
    }
    __syncthreads();

    // ---- encoder layer 1: enc1 -> h2[1][t][r] ----
    {
        float a[R_];
        float bb = b1[t];
        #pragma unroll
        for (int r = 0; r < R_; r++) a[r] = bb;
        #pragma unroll
        for (int k = 0; k < 7; k++) {
            float w = g_W1T[k * 256 + t];
            #pragma unroll
            for (int r = 0; r < R_; r++) a[r] += metas[r][k] * w;
        }
        #pragma unroll
        for (int r = 0; r < R_; r++) h2[1][t][r] = fmaxf(a[r], 0.f);
    }
    __syncthreads();

    // ---- encoder layer 2: h0 -> h2[0], c0 in regs ----
    u64 c2[7];
    {
        u64 ha[7], ca[7];
        u64 bh = dup2(b2[t]), bc = dup2(b2[256 + t]);
        #pragma unroll
        for (int p = 0; p < 7; p++) { ha[p] = bh; ca[p] = bc; }
        const float* hrow = &h2[1][0][0];
        #pragma unroll 2
        for (int k = 0; k < 256; k++) {
            u64 wh = dup2(g_W2T[k * 512 + t]);
            u64 wc = dup2(g_W2T[k * 512 + 256 + t]);
            const float* hb = hrow + k * HS;
            F4 hA, hB, hC; F2 hD;
            hA.f = *reinterpret_cast<const float4*>(hb);
            hB.f = *reinterpret_cast<const float4*>(hb + 4);
            hC.f = *reinterpret_cast<const float4*>(hb + 8);
            hD.f = *reinterpret_cast<const float2*>(hb + 12);
            u64 h[7] = { hA.u[0], hA.u[1], hB.u[0], hB.u[1], hC.u[0], hC.u[1], hD.u };
            #pragma unroll
            for (int p = 0; p < 7; p++) {
                ha[p] = fma2(h[p], wh, ha[p]);
                ca[p] = fma2(h[p], wc, ca[p]);
            }
        }
        #pragma unroll
        for (int p = 0; p < 7; p++) {
            float2 hv = unpk(ha[p]);
            float2 cv = unpk(ca[p]);
            h2[0][t][2 * p]     = fmaxf(hv.x, 0.f);
            h2[0][t][2 * p + 1] = fmaxf(hv.y, 0.f);
            c2[p] = pk(fmaxf(cv.x, 0.f), fmaxf(cv.y, 0.f));
        }
    }
    __syncthreads();

    const int j2 = t & 127;
    const int hi = t >> 7;
    float* outp = out + (long)row0 * (T_eff * 3);
    int cur = 0;

    // =====================  LSTM scan  =====================
    for (int step = 0; step < T_eff; step++) {
        const int nxt = cur ^ 1;

        // ---- gate accumulation: gates[j] = bias + x.Wih + h.Whh ----
        u64 ai[7], af[7], ag[7], ao[7];
        {
            F4 bb0, bb1;
            bb0.f = g_BiasD[t * 2 + 0];
            bb1.f = g_BiasD[t * 2 + 1];
            #pragma unroll
            for (int p = 0; p < 7; p++) {
                ai[p] = bb0.u[0]; af[p] = bb0.u[1];
                ag[p] = bb1.u[0]; ao[p] = bb1.u[1];
            }
            #pragma unroll
            for (int e = 0; e < 3; e++) {
                F4 wA, wB;
                wA.f = g_WihD[(e * 256 + t) * 2 + 0];
                wB.f = g_WihD[(e * 256 + t) * 2 + 1];
                #pragma unroll
                for (int p = 0; p < 7; p++) {
                    u64 xp = *reinterpret_cast<const u64*>(&xs[e][2 * p]);
                    ai[p] = fma2(xp, wA.u[0], ai[p]);
                    af[p] = fma2(xp, wA.u[1], af[p]);
                    ag[p] = fma2(xp, wB.u[0], ag[p]);
                    ao[p] = fma2(xp, wB.u[1], ao[p]);
                }
            }
        }
        {
            // 4-slice blocks, ping-pong prefetched one block ahead.
            // Each slice = 2 coalesced LDG.128 of pre-duplicated weights.
            const float4* wp   = g_WhhD + t * 2;   // slice k at wp[k*512], wp[k*512+1]
            const float*  hrow = &h2[cur][0][0];
            F4 A[8], Bv[8];
            #pragma unroll
            for (int s = 0; s < 4; s++) {
                A[2 * s].f     = wp[s * 512];
                A[2 * s + 1].f = wp[s * 512 + 1];
            }
            #pragma unroll 1
            for (int kb = 0; kb < 248; kb += 8) {
                #pragma unroll
                for (int s = 0; s < 4; s++) {
                    Bv[2 * s].f     = wp[(kb + 4 + s) * 512];
                    Bv[2 * s + 1].f = wp[(kb + 4 + s) * 512 + 1];
                }
                const float* hb = hrow + kb * HS;
                mac_k(A[0], A[1], hb,          ai, af, ag, ao);
                mac_k(A[2], A[3], hb + HS,     ai, af, ag, ao);
                mac_k(A[4], A[5], hb + 2 * HS, ai, af, ag, ao);
                mac_k(A[6], A[7], hb + 3 * HS, ai, af, ag, ao);
                #pragma unroll
                for (int s = 0; s < 4; s++) {
                    A[2 * s].f     = wp[(kb + 8 + s) * 512];
                    A[2 * s + 1].f = wp[(kb + 8 + s) * 512 + 1];
                }
                mac_k(Bv[0], Bv[1], hb + 4 * HS, ai, af, ag, ao);
                mac_k(Bv[2], Bv[3], hb + 5 * HS, ai, af, ag, ao);
                mac_k(Bv[4], Bv[5], hb + 6 * HS, ai, af, ag, ao);
                mac_k(Bv[6], Bv[7], hb + 7 * HS, ai, af, ag, ao);
            }
            {   // epilogue: k = 248..255 (A holds 248..251)
                #pragma unroll
                for (int s = 0; s < 4; s++) {
                    Bv[2 * s].f     = wp[(252 + s) * 512];
                    Bv[2 * s + 1].f = wp[(252 + s) * 512 + 1];
                }
                const float* hb = hrow + 248 * HS;
                mac_k(A[0], A[1], hb,          ai, af, ag, ao);
                mac_k(A[2], A[3], hb + HS,     ai, af, ag, ao);
                mac_k(A[4], A[5], hb + 2 * HS, ai, af, ag, ao);
                mac_k(A[6], A[7], hb + 3 * HS, ai, af, ag, ao);
                mac_k(Bv[0], Bv[1], hb + 4 * HS, ai, af, ag, ao);
                mac_k(Bv[2], Bv[3], hb + 5 * HS, ai, af, ag, ao);
                mac_k(Bv[4], Bv[5], hb + 6 * HS, ai, af, ag, ao);
                mac_k(Bv[6], Bv[7], hb + 7 * HS, ai, af, ag, ao);
            }
        }

        // ---- elementwise LSTM cell update: write new h into the OTHER buffer ----
        {
            float hn[R_];
            #pragma unroll
            for (int p = 0; p < 7; p++) {
                float2 iv = unpk(ai[p]), fv = unpk(af[p]);
                float2 gv = unpk(ag[p]), ov = unpk(ao[p]);
                float2 cv = unpk(c2[p]);
                float c0n = sigmoidf_(fv.x) * cv.x + sigmoidf_(iv.x) * tanhf_(gv.x);
                float c1n = sigmoidf_(fv.y) * cv.y + sigmoidf_(iv.y) * tanhf_(gv.y);
                hn[2 * p]     = sigmoidf_(ov.x) * tanhf_(c0n);
                hn[2 * p + 1] = sigmoidf_(ov.y) * tanhf_(c1n);
                c2[p] = pk(c0n, c1n);
            }
            float* hrow = &h2[nxt][t][0];
            *reinterpret_cast<float4*>(hrow + 0)  = make_float4(hn[0], hn[1], hn[2], hn[3]);
            *reinterpret_cast<float4*>(hrow + 4)  = make_float4(hn[4], hn[5], hn[6], hn[7]);
            *reinterpret_cast<float4*>(hrow + 8)  = make_float4(hn[8], hn[9], hn[10], hn[11]);
            *reinterpret_cast<float2*>(hrow + 12) = make_float2(hn[12], hn[13]);
        }
        __syncthreads();   // S1: new h visible; everyone done reading xs

        // ---- decoder layer 1 (ALL 256 threads): z = relu(h . Wo1^T + bo1) ----
        {
            const float2* wo   = g_Wo1D + j2;     // pre-duplicated (w,w)
            const float* hrow2 = &h2[nxt][0][0];
            u64 bz = dup2(bo1s[j2]);
            F2 wv[8];
            #pragma unroll
            for (int i = 0; i < 8; i++) wv[i].f = wo[i * 128];
            if (hi == 0) {
                u64 z0 = bz, z1 = bz, z2 = bz, z3 = bz;           // rows 0..7
                #pragma unroll 1
                for (int kb = 0; kb < 248; kb += 8) {
                    F2 nv[8];
                    #pragma unroll
                    for (int i = 0; i < 8; i++) nv[i].f = wo[(kb + 8 + i) * 128];
                    #pragma unroll
                    for (int i = 0; i < 8; i++) {
                        const float* hb = hrow2 + (kb + i) * HS;
                        F4 A2, B2;
                        A2.f = *reinterpret_cast<const float4*>(hb);
                        B2.f = *reinterpret_cast<const float4*>(hb + 4);
                        z0 = fma2(A2.u[0], wv[i].u, z0);
                        z1 = fma2(A2.u[1], wv[i].u, z1);
                        z2 = fma2(B2.u[0], wv[i].u, z2);
                        z3 = fma2(B2.u[1], wv[i].u, z3);
                    }
                    #pragma unroll
                    for (int i = 0; i < 8; i++) wv[i] = nv[i];
                }
                #pragma unroll
                for (int i = 0; i < 8; i++) {
                    const float* hb = hrow2 + (248 + i) * HS;
                    F4 A2, B2;
                    A2.f = *reinterpret_cast<const float4*>(hb);
                    B2.f = *reinterpret_cast<const float4*>(hb + 4);
                    z0 = fma2(A2.u[0], wv[i].u, z0);
                    z1 = fma2(A2.u[1], wv[i].u, z1);
                    z2 = fma2(B2.u[0], wv[i].u, z2);
                    z3 = fma2(B2.u[1], wv[i].u, z3);
                }
                float2 v;
                v = unpk(z0); zb[0][j2] = fmaxf(v.x, 0.f); zb[1][j2] = fmaxf(v.y, 0.f);
                v = unpk(z1); zb[2][j2] = fmaxf(v.x, 0.f); zb[3][j2] = fmaxf(v.y, 0.f);
                v = unpk(z2); zb[4][j2] = fmaxf(v.x, 0.f); zb[5][j2] = fmaxf(v.y, 0.f);
                v = unpk(z3); zb[6][j2] = fmaxf(v.x, 0.f); zb[7][j2] = fmaxf(v.y, 0.f);
            } else {
                u64 z0 = bz, z1 = bz, z2 = bz;                    // rows 8..13
                #pragma unroll 1
                for (int kb = 0; kb < 248; kb += 8) {
                    F2 nv[8];
                    #pragma unroll
                    for (int i = 0; i < 8; i++) nv[i].f = wo[(kb + 8 + i) * 128];
                    #pragma unroll
                    for (int i = 0; i < 8; i++) {
                        const float* hb = hrow2 + (kb + i) * HS;
                        F4 Cv; F2 Dv;
                        Cv.f = *reinterpret_cast<const float4*>(hb + 8);
                        Dv.f = *reinterpret_cast<const float2*>(hb + 12);
                        z0 = fma2(Cv.u[0], wv[i].u, z0);
                        z1 = fma2(Cv.u[1], wv[i].u, z1);
                        z2 = fma2(Dv.u,    wv[i].u, z2);
                    }
                    #pragma unroll
                    for (int i = 0; i < 8; i++) wv[i] = nv[i];
                }
                #pragma unroll
                for (int i = 0; i < 8; i++) {
                    const float* hb = hrow2 + (248 + i) * HS;
                    F4 Cv; F2 Dv;
                    Cv.f = *reinterpret_cast<const float4*>(hb + 8);
                    Dv.f = *reinterpret_cast<const float2*>(hb + 12);
                    z0 = fma2(Cv.u[0], wv[i].u, z0);
                    z1 = fma2(Cv.u[1], wv[i].u, z1);
                    z2 = fma2(Dv.u,    wv[i].u, z2);
                }
                float2 v;
                v = unpk(z0); zb[ 8][j2] = fmaxf(v.x, 0.f); zb[ 9][j2] = fmaxf(v.y, 0.f);
                v = unpk(z1); zb[10][j2] = fmaxf(v.x, 0.f); zb[11][j2] = fmaxf(v.y, 0.f);
                v = unpk(z2); zb[12][j2] = fmaxf(v.x, 0.f); zb[13][j2] = fmaxf(v.y, 0.f);
            }
        }
        __syncthreads();   // S2: zb ready

        // ---- decoder layer 2: y = z . Wo2^T + bo2 ; feed back as next x ----
        if (t < 42) {
            int r = t / 3, o = t - 3 * (t / 3);
            const float* zr = zb[r];
            const float* w2 = &wo2s[o * 128];
            float4 acc4 = make_float4(0.f, 0.f, 0.f, 0.f);
            #pragma unroll 8
            for (int j = 0; j < 128; j += 4) {
                float4 zv = *reinterpret_cast<const float4*>(zr + j);
                float4 wv2 = *reinterpret_cast<const float4*>(w2 + j);
                acc4.x += zv.x * wv2.x;
                acc4.y += zv.y * wv2.y;
                acc4.z += zv.z * wv2.z;
                acc4.w += zv.w * wv2.w;
            }
            float acc = bo2s[o] + ((acc4.x + acc4.y) + (acc4.z + acc4.w));
            if (row0 + r < B_) outp[r * (T_eff * 3) + step * 3 + o] = acc;
            xs[o][r] = acc;
        }
        __syncthreads();   // S3: xs ready for next step

        cur = nxt;
    }
}

// ---------------------------------------------------------------------------
// Launch
// ---------------------------------------------------------------------------
extern "C" void kernel_launch(void* const* d_in, const int* in_sizes, int n_in,
                              void* d_out, int out_size)
{
    const float* meta = (const float*)d_in[0];
    // d_in[1] = target_seq_len (encoded by the output shape)
    const float* W1   = (const float*)d_in[2];
    const float* b1   = (const float*)d_in[3];
    const float* W2   = (const float*)d_in[4];
    const float* b2   = (const float*)d_in[5];
    const float* Wih  = (const float*)d_in[6];
    const float* Whh  = (const float*)d_in[7];
    const float* bih  = (const float*)d_in[8];
    const float* bhh  = (const float*)d_in[9];
    const float* Wo1  = (const float*)d_in[10];
    const float* bo1  = (const float*)d_in[11];
    const float* Wo2  = (const float*)d_in[12];
    const float* bo2  = (const float*)d_in[13];
    float* out = (float*)d_out;

    int T_eff = out_size / (B_ * 3);   // equals target_seq_len by output shape

    prep_kernel<<<256, 256>>>(W1, W2, Wih, Whh, bih, bhh, Wo1);
    lstm_kernel<<<NCTA, 256>>>(meta, b1, b2, bo1, Wo2, bo2, out, T_eff);
}

// round 15
// speedup vs baseline: 1.3263x; 1.3263x over previous
#include <cuda_runtime.h>

// Problem constants (fixed by the dataset)
#define B_   4096
#define H_   256
#define R_   14              // rows per CTA
#define NCTA 293             // ceil(4096/14)
#define HS   20              // h2 row stride in floats (80B: 16B-aligned, 4-way STS spread)

// ---------------------------------------------------------------------------
// Device scratch (no dynamic allocation allowed)
// ---------------------------------------------------------------------------
__device__ float4 g_packWhh[256 * 256];  // [k][j] -> (Whh_i, Whh_f, Whh_g, Whh_o)[j][k]
__device__ float4 g_packWih[3 * 256];    // [e][j]
__device__ float4 g_packBias[256];       // [j]    -> bih+bhh per gate
__device__ float  g_W2T[256 * 512];      // [k][j]
__device__ float  g_Wo1T[256 * 128];     // [k][j2]
__device__ float  g_W1T[7 * 256];        // [k][j]

// ---------------------------------------------------------------------------
// Prep kernel: transpose / gate-pack weights for coalesced LDG.128 streaming
// ---------------------------------------------------------------------------
__global__ void prep_kernel(const float* __restrict__ W1,
                            const float* __restrict__ W2,
                            const float* __restrict__ Wih,
                            const float* __restrict__ Whh,
                            const float* __restrict__ bih,
                            const float* __restrict__ bhh,
                            const float* __restrict__ Wo1)
{
    int k = blockIdx.x;    // 0..255
    int j = threadIdx.x;   // 0..255

    g_packWhh[k * 256 + j] = make_float4(Whh[(0   + j) * 256 + k],
                                         Whh[(256 + j) * 256 + k],
                                         Whh[(512 + j) * 256 + k],
                                         Whh[(768 + j) * 256 + k]);
    g_W2T[k * 512 + j]       = W2[(0   + j) * 256 + k];
    g_W2T[k * 512 + 256 + j] = W2[(256 + j) * 256 + k];
    if (j < 128) g_Wo1T[k * 128 + j] = Wo1[j * 256 + k];
    if (k < 7)   g_W1T[k * 256 + j] = W1[j * 7 + k];
    if (k < 3)   g_packWih[k * 256 + j] = make_float4(Wih[(0   + j) * 3 + k],
                                                      Wih[(256 + j) * 3 + k],
                                                      Wih[(512 + j) * 3 + k],
                                                      Wih[(768 + j) * 3 + k]);
    if (k == 0)  g_packBias[j] = make_float4(bih[0   + j] + bhh[0   + j],
                                             bih[256 + j] + bhh[256 + j],
                                             bih[512 + j] + bhh[512 + j],
                                             bih[768 + j] + bhh[768 + j]);
}

// ---------------------------------------------------------------------------
// Packed f32x2 helpers (sm_100+): doubles fp32 FMA throughput per issue
// ---------------------------------------------------------------------------
typedef unsigned long long u64;

union F4 { float4 f; u64 u[2]; };
union F2 { float2 f; u64 u; };

__device__ __forceinline__ u64 fma2(u64 a, u64 b, u64 c) {
    u64 d;
    asm("fma.rn.f32x2 %0, %1, %2, %3;" : "=l"(d) : "l"(a), "l"(b), "l"(c));
    return d;
}
__device__ __forceinline__ u64 dup2(float x) {
    u64 d; unsigned xi = __float_as_uint(x);
    asm("mov.b64 %0, {%1, %2};" : "=l"(d) : "r"(xi), "r"(xi));
    return d;
}
__device__ __forceinline__ u64 pk(float lo, float hi) {
    u64 d;
    asm("mov.b64 %0, {%1, %2};" : "=l"(d)
        : "r"(__float_as_uint(lo)), "r"(__float_as_uint(hi)));
    return d;
}
__device__ __forceinline__ float2 unpk(u64 a) {
    unsigned lo, hi;
    asm("mov.b64 {%0, %1}, %2;" : "=r"(lo), "=r"(hi) : "l"(a));
    return make_float2(__uint_as_float(lo), __uint_as_float(hi));
}

__device__ __forceinline__ float sigmoidf_(float x) {
    return __fdividef(1.f, 1.f + __expf(-x));
}
// branch-free accurate tanh: 1 - 2/(e^{2x}+1); inf-safe, ~1e-6 err
__device__ __forceinline__ float tanhf_(float x) {
    float e = __expf(2.f * x);
    return 1.f - __fdividef(2.f, e + 1.f);
}

// h operands for one k-slice: 14 rows as 7 u64 pairs (3 LDS.128 + 1 LDS.64)
struct H7 { F4 A, B, C; F2 D; };

__device__ __forceinline__ void loadh(H7& h, const float* __restrict__ hb) {
    h.A.f = *reinterpret_cast<const float4*>(hb);
    h.B.f = *reinterpret_cast<const float4*>(hb + 4);
    h.C.f = *reinterpret_cast<const float4*>(hb + 8);
    h.D.f = *reinterpret_cast<const float2*>(hb + 12);
}

// 4-gate MAC with PRELOADED h: 4 dup2 + 28 fma2, no loads
__device__ __forceinline__ void mac_h(const float4 w, const H7& h,
                                      u64* ai, u64* af, u64* ag, u64* ao)
{
    u64 wx = dup2(w.x), wy = dup2(w.y), wz = dup2(w.z), ww = dup2(w.w);
    u64 hv[7] = { h.A.u[0], h.A.u[1], h.B.u[0], h.B.u[1], h.C.u[0], h.C.u[1], h.D.u };
    #pragma unroll
    for (int p = 0; p < 7; p++) {
        ai[p] = fma2(hv[p], wx, ai[p]);
        af[p] = fma2(hv[p], wy, af[p]);
        ag[p] = fma2(hv[p], wz, ag[p]);
        ao[p] = fma2(hv[p], ww, ao[p]);
    }
}

// ---------------------------------------------------------------------------
// Main persistent kernel: one CTA handles 14 batch rows end-to-end.
// ---------------------------------------------------------------------------
__global__ void __launch_bounds__(256, 2)
lstm_kernel(const float* __restrict__ meta,
            const float* __restrict__ b1,
            const float* __restrict__ b2,
            const float* __restrict__ bo1,
            const float* __restrict__ Wo2,
            const float* __restrict__ bo2,
            float* __restrict__ out,
            int T_eff)
{
    __shared__ __align__(16) float h2[2][256][HS]; // double-buffered h [buf][k][row]
    __shared__ __align__(16) float xs[3][16];      // [elem][row] current x (fed-back y)
    __shared__ __align__(16) float zb[14][132];    // decoder hidden [row][j2]
    __shared__ float metas[14][8];
    __shared__ __align__(16) float wo2s[3 * 128];
    __shared__ float bo1s[128];
    __shared__ float bo2s[4];
    __shared__ float psum[128];                    // decoder-2 partials

    const int t    = threadIdx.x;
    const int row0 = blockIdx.x * R_;

    // ---- stage small tensors (row indices clamped for the partial last CTA) ----
    if (t < 112) {
        int r = t >> 3, e = t & 7;
        int g = row0 + r; if (g > B_ - 1) g = B_ - 1;
        metas[r][e] = (e < 7) ? meta[g * 7 + e] : 0.f;
    }
    if (t < 128) bo1s[t] = bo1[t];
    wo2s[t] = Wo2[t];
    if (t < 128) wo2s[256 + t] = Wo2[256 + t];
    if (t < 3)   bo2s[t] = bo2[t];
    if (t < 42) {
        int r = t / 3, o = t - 3 * (t / 3);
        int g = row0 + r; if (g > B_ - 1) g = B_ - 1;
        xs[o][r] = meta[g * 7 + o];   // x0 = metadata[:, :3]
    }
    __syncthreads();

    // ---- encoder layer 1: enc1 -> h2[1][t][r] ----
    {
        float a[R_];
        float bb = b1[t];
        #pragma unroll
        for (int r = 0; r < R_; r++) a[r] = bb;
        #pragma unroll
        for (int k = 0; k < 7; k++) {
            float w = g_W1T[k * 256 + t];
            #pragma unroll
            for (int r = 0; r < R_; r++) a[r] += metas[r][k] * w;
        }
        #pragma unroll
        for (int r = 0; r < R_; r++) h2[1][t][r] = fmaxf(a[r], 0.f);
    }
    __syncthreads();

    // ---- encoder layer 2: h0 -> h2[0], c0 in regs ----
    u64 c2[7];
    {
        u64 ha[7], ca[7];
        u64 bh = dup2(b2[t]), bc = dup2(b2[256 + t]);
        #pragma unroll
        for (int p = 0; p < 7; p++) { ha[p] = bh; ca[p] = bc; }
        const float* hrow = &h2[1][0][0];
        #pragma unroll 2
        for (int k = 0; k < 256; k++) {
            u64 wh = dup2(g_W2T[k * 512 + t]);
            u64 wc = dup2(g_W2T[k * 512 + 256 + t]);
            H7 h; loadh(h, hrow + k * HS);
            u64 hv[7] = { h.A.u[0], h.A.u[1], h.B.u[0], h.B.u[1],
                          h.C.u[0], h.C.u[1], h.D.u };
            #pragma unroll
            for (int p = 0; p < 7; p++) {
                ha[p] = fma2(hv[p], wh, ha[p]);
                ca[p] = fma2(hv[p], wc, ca[p]);
            }
        }
        #pragma unroll
        for (int p = 0; p < 7; p++) {
            float2 hv = unpk(ha[p]);
            float2 cv = unpk(ca[p]);
            h2[0][t][2 * p]     = fmaxf(hv.x, 0.f);
            h2[0][t][2 * p + 1] = fmaxf(hv.y, 0.f);
            c2[p] = pk(fmaxf(cv.x, 0.f), fmaxf(cv.y, 0.f));
        }
    }
    __syncthreads();

    const int j2 = t & 127;
    const int hi = t >> 7;
    float* outp = out + (long)row0 * (T_eff * 3);
    int cur = 0;

    // =====================  LSTM scan  =====================
    for (int step = 0; step < T_eff; step++) {
        const int nxt = cur ^ 1;

        // ---- gate accumulation: gates[j] = bias + x.Wih + h.Whh ----
        u64 ai[7], af[7], ag[7], ao[7];
        {
            float4 bb = g_packBias[t];
            u64 bi = dup2(bb.x), bf = dup2(bb.y), bg = dup2(bb.z), bo = dup2(bb.w);
            #pragma unroll
            for (int p = 0; p < 7; p++) { ai[p] = bi; af[p] = bf; ag[p] = bg; ao[p] = bo; }
            #pragma unroll
            for (int e = 0; e < 3; e++) {
                float4 we = g_packWih[e * 256 + t];
                u64 wx = dup2(we.x), wy = dup2(we.y), wz = dup2(we.z), ww = dup2(we.w);
                #pragma unroll
                for (int p = 0; p < 7; p++) {
                    u64 xp = *reinterpret_cast<const u64*>(&xs[e][2 * p]);
                    ai[p] = fma2(xp, wx, ai[p]);
                    af[p] = fma2(xp, wy, af[p]);
                    ag[p] = fma2(xp, wz, ag[p]);
                    ao[p] = fma2(xp, ww, ao[p]);
                }
            }
        }
        {
            // Weights: 8-deep LDG ping-pong (a/b groups).
            // h operands: 2-slot register ping-pong — the LDS for slice k+1 are
            // in flight while slice k's 28-FFMA2 chain executes.
            const float4* wp   = g_packWhh + t;
            const float*  hrow = &h2[cur][0][0];
            H7 hh0, hh1;
            loadh(hh0, hrow);                       // h(k=0)
            float4 a0 = wp[0 * 256], a1 = wp[1 * 256],
                   a2 = wp[2 * 256], a3 = wp[3 * 256];
            #pragma unroll 1
            for (int kb = 0; kb < 248; kb += 8) {
                float4 b0 = wp[(kb + 4) * 256], b1 = wp[(kb + 5) * 256],
                       b2w = wp[(kb + 6) * 256], b3 = wp[(kb + 7) * 256];
                const float* hb = hrow + kb * HS;
                loadh(hh1, hb + 1 * HS);  mac_h(a0, hh0, ai, af, ag, ao);
                loadh(hh0, hb + 2 * HS);  mac_h(a1, hh1, ai, af, ag, ao);
                loadh(hh1, hb + 3 * HS);  mac_h(a2, hh0, ai, af, ag, ao);
                loadh(hh0, hb + 4 * HS);  mac_h(a3, hh1, ai, af, ag, ao);
                a0 = wp[(kb + 8) * 256];  a1 = wp[(kb + 9) * 256];
                a2 = wp[(kb + 10) * 256]; a3 = wp[(kb + 11) * 256];
                loadh(hh1, hb + 5 * HS);  mac_h(b0,  hh0, ai, af, ag, ao);
                loadh(hh0, hb + 6 * HS);  mac_h(b1,  hh1, ai, af, ag, ao);
                loadh(hh1, hb + 7 * HS);  mac_h(b2w, hh0, ai, af, ag, ao);
                loadh(hh0, hb + 8 * HS);  mac_h(b3,  hh1, ai, af, ag, ao);
            }
            {   // epilogue: k = 248..255 (hh0 holds h(248); a holds w(248..251))
                float4 b0 = wp[252 * 256], b1 = wp[253 * 256],
                       b2w = wp[254 * 256], b3 = wp[255 * 256];
                const float* hb = hrow + 248 * HS;
                loadh(hh1, hb + 1 * HS);  mac_h(a0, hh0, ai, af, ag, ao);
                loadh(hh0, hb + 2 * HS);  mac_h(a1, hh1, ai, af, ag, ao);
                loadh(hh1, hb + 3 * HS);  mac_h(a2, hh0, ai, af, ag, ao);
                loadh(hh0, hb + 4 * HS);  mac_h(a3, hh1, ai, af, ag, ao);
                loadh(hh1, hb + 5 * HS);  mac_h(b0,  hh0, ai, af, ag, ao);
                loadh(hh0, hb + 6 * HS);  mac_h(b1,  hh1, ai, af, ag, ao);
                loadh(hh1, hb + 7 * HS);  mac_h(b2w, hh0, ai, af, ag, ao);
                                          mac_h(b3,  hh1, ai, af, ag, ao);
            }
        }

        // ---- elementwise LSTM cell update: write new h into the OTHER buffer ----
        {
            float hn[R_];
            #pragma unroll
            for (int p = 0; p < 7; p++) {
                float2 iv = unpk(ai[p]), fv = unpk(af[p]);
                float2 gv = unpk(ag[p]), ov = unpk(ao[p]);
                float2 cv = unpk(c2[p]);
                float c0n = sigmoidf_(fv.x) * cv.x + sigmoidf_(iv.x) * tanhf_(gv.x);
                float c1n = sigmoidf_(fv.y) * cv.y + sigmoidf_(iv.y) * tanhf_(gv.y);
                hn[2 * p]     = sigmoidf_(ov.x) * tanhf_(c0n);
                hn[2 * p + 1] = sigmoidf_(ov.y) * tanhf_(c1n);
                c2[p] = pk(c0n, c1n);
            }
            float* hrow = &h2[nxt][t][0];
            *reinterpret_cast<float4*>(hrow + 0)  = make_float4(hn[0], hn[1], hn[2], hn[3]);
            *reinterpret_cast<float4*>(hrow + 4)  = make_float4(hn[4], hn[5], hn[6], hn[7]);
            *reinterpret_cast<float4*>(hrow + 8)  = make_float4(hn[8], hn[9], hn[10], hn[11]);
            *reinterpret_cast<float2*>(hrow + 12) = make_float2(hn[12], hn[13]);
        }
        __syncthreads();   // S1: new h visible; everyone done reading xs

        // ---- decoder layer 1 (ALL 256 threads): z = relu(h . Wo1^T + bo1) ----
        {
            const float* wo    = g_Wo1T + j2;
            const float* hrow2 = &h2[nxt][0][0];
            u64 bz = dup2(bo1s[j2]);
            float wv[8];
            #pragma unroll
            for (int i = 0; i < 8; i++) wv[i] = wo[i * 128];
            if (hi == 0) {
                u64 z0 = bz, z1 = bz, z2 = bz, z3 = bz;           // rows 0..7
                #pragma unroll 1
                for (int kb = 0; kb < 248; kb += 8) {
                    float nv[8];
                    #pragma unroll
                    for (int i = 0; i < 8; i++) nv[i] = wo[(kb + 8 + i) * 128];
                    #pragma unroll
                    for (int i = 0; i < 8; i++) {
                        u64 wd = dup2(wv[i]);
                        const float* hb = hrow2 + (kb + i) * HS;
                        F4 A, Bv;
                        A.f  = *reinterpret_cast<const float4*>(hb);
                        Bv.f = *reinterpret_cast<const float4*>(hb + 4);
                        z0 = fma2(A.u[0],  wd, z0);
                        z1 = fma2(A.u[1],  wd, z1);
                        z2 = fma2(Bv.u[0], wd, z2);
                        z3 = fma2(Bv.u[1], wd, z3);
                    }
                    #pragma unroll
                    for (int i = 0; i < 8; i++) wv[i] = nv[i];
                }
                #pragma unroll
                for (int i = 0; i < 8; i++) {
                    u64 wd = dup2(wv[i]);
                    const float* hb = hrow2 + (248 + i) * HS;
                    F4 A, Bv;
                    A.f  = *reinterpret_cast<const float4*>(hb);
                    Bv.f = *reinterpret_cast<const float4*>(hb + 4);
                    z0 = fma2(A.u[0],  wd, z0);
                    z1 = fma2(A.u[1],  wd, z1);
                    z2 = fma2(Bv.u[0], wd, z2);
                    z3 = fma2(Bv.u[1], wd, z3);
                }
                float2 v;
                v = unpk(z0); zb[0][j2] = fmaxf(v.x, 0.f); zb[1][j2] = fmaxf(v.y, 0.f);
                v = unpk(z1); zb[2][j2] = fmaxf(v.x, 0.f); zb[3][j2] = fmaxf(v.y, 0.f);
                v = unpk(z2); zb[4][j2] = fmaxf(v.x, 0.f); zb[5][j2] = fmaxf(v.y, 0.f);
                v = unpk(z3); zb[6][j2] = fmaxf(v.x, 0.f); zb[7][j2] = fmaxf(v.y, 0.f);
            } else {
                u64 z0 = bz, z1 = bz, z2 = bz;                    // rows 8..13
                #pragma unroll 1
                for (int kb = 0; kb < 248; kb += 8) {
                    float nv[8];
                    #pragma unroll
                    for (int i = 0; i < 8; i++) nv[i] = wo[(kb + 8 + i) * 128];
                    #pragma unroll
                    for (int i = 0; i < 8; i++) {
                        u64 wd = dup2(wv[i]);
                        const float* hb = hrow2 + (kb + i) * HS;
                        F4 Cv; F2 Dv;
                        Cv.f = *reinterpret_cast<const float4*>(hb + 8);
                        Dv.f = *reinterpret_cast<const float2*>(hb + 12);
                        z0 = fma2(Cv.u[0], wd, z0);
                        z1 = fma2(Cv.u[1], wd, z1);
                        z2 = fma2(Dv.u,    wd, z2);
                    }
                    #pragma unroll
                    for (int i = 0; i < 8; i++) wv[i] = nv[i];
                }
                #pragma unroll
                for (int i = 0; i < 8; i++) {
                    u64 wd = dup2(wv[i]);
                    const float* hb = hrow2 + (248 + i) * HS;
                    F4 Cv; F2 Dv;
                    Cv.f = *reinterpret_cast<const float4*>(hb + 8);
                    Dv.f = *reinterpret_cast<const float2*>(hb + 12);
                    z0 = fma2(Cv.u[0], wd, z0);
                    z1 = fma2(Cv.u[1], wd, z1);
                    z2 = fma2(Dv.u,    wd, z2);
                }
                float2 v;
                v = unpk(z0); zb[ 8][j2] = fmaxf(v.x, 0.f); zb[ 9][j2] = fmaxf(v.y, 0.f);
                v = unpk(z1); zb[10][j2] = fmaxf(v.x, 0.f); zb[11][j2] = fmaxf(v.y, 0.f);
                v = unpk(z2); zb[12][j2] = fmaxf(v.x, 0.f); zb[13][j2] = fmaxf(v.y, 0.f);
            }
        }
        __syncthreads();   // S2: zb ready

        // ---- decoder layer 2 (parallel, 126 threads): y = z . Wo2^T + bo2 ----
        if (t < 128) {
            if (t < 126) {
                int pair = t / 3;            // 0..41 -> (r, o)
                int part = t - 3 * pair;     // 0..2  -> j-range third
                int r = pair / 3, o = pair - 3 * (pair / 3);
                int j0 = part * 44;
                int j1 = (part == 2) ? 128 : (j0 + 44);
                const float* zr = zb[r];
                const float* w2 = &wo2s[o * 128];
                float4 a4 = make_float4(0.f, 0.f, 0.f, 0.f);
                #pragma unroll 4
                for (int j = j0; j < j1; j += 4) {
                    float4 zv  = *reinterpret_cast<const float4*>(zr + j);
                    float4 wv2 = *reinterpret_cast<const float4*>(w2 + j);
                    a4.x += zv.x * wv2.x;
                    a4.y += zv.y * wv2.y;
                    a4.z += zv.z * wv2.z;
                    a4.w += zv.w * wv2.w;
                }
                psum[t] = (a4.x + a4.y) + (a4.z + a4.w);
            }
            asm volatile("bar.sync 1, 128;" ::: "memory");   // warps 0-3 only
            if (t < 42) {
                int r = t / 3, o = t - 3 * (t / 3);
                float acc = bo2s[o] + psum[3 * t] + psum[3 * t + 1] + psum[3 * t + 2];
                if (row0 + r < B_) outp[r * (T_eff * 3) + step * 3 + o] = acc;
                xs[o][r] = acc;
            }
        }
        __syncthreads();   // S3: xs ready for next step

        cur = nxt;
    }
}

// ---------------------------------------------------------------------------
// Launch
// ---------------------------------------------------------------------------
extern "C" void kernel_launch(void* const* d_in, const int* in_sizes, int n_in,
                              void* d_out, int out_size)
{
    const float* meta = (const float*)d_in[0];
    // d_in[1] = target_seq_len (encoded by the output shape)
    const float* W1   = (const float*)d_in[2];
    const float* b1   = (const float*)d_in[3];
    const float* W2   = (const float*)d_in[4];
    const float* b2   = (const float*)d_in[5];
    const float* Wih  = (const float*)d_in[6];
    const float* Whh  = (const float*)d_in[7];
    const float* bih  = (const float*)d_in[8];
    const float* bhh  = (const float*)d_in[9];
    const float* Wo1  = (const float*)d_in[10];
    const float* bo1  = (const float*)d_in[11];
    const float* Wo2  = (const float*)d_in[12];
    const float* bo2  = (const float*)d_in[13];
    float* out = (float*)d_out;

    int T_eff = out_size / (B_ * 3);   // equals target_seq_len by output shape

    prep_kernel<<<256, 256>>>(W1, W2, Wih, Whh, bih, bhh, Wo1);
    lstm_kernel<<<NCTA, 256>>>(meta, b1, b2, bo1, Wo2, bo2, out, T_eff);
}